// round 16
// baseline (speedup 1.0000x reference)
#include <cuda_runtime.h>
#include <cuda_fp16.h>

#define NANG  4
#define NELEM 128
#define NZ    192
#define NX    192
#define NPIX  (NZ * NX)
#define NSAMP 2048
#define NTOT  (NANG * NELEM * NSAMP)

#define PI_F      3.14159265359f
#define HALF_PI_F 1.57079632679f
#define FS_F      20832000.0f
#define C_F       1540.0f
#define FDEMOD_F  5208000.0f
#define FSoC      (FS_F / C_F)

// Scratch (static device globals -- no allocation)
// g_pair[s] = ( R[s], R[s+1] ) where R[s] = rot((pi/2)*s) . (i[s], q[s]),
// each R a half2, packed so one contrib = ONE aligned LDG.64.
__device__ float2 g_pair[NTOT];                 // 8 MB
__device__ float  g_acc[NANG * 4][NPIX];        // per-(angle,half) partials

__device__ __forceinline__ unsigned h2bits(float i, float q) {
    __half2 h = __floats2half2_rn(i, q);
    return *reinterpret_cast<unsigned*>(&h);
}

// ---------------------------------------------------------------------------
// Pass 1: build the pair-duplicated PRE-ROTATED fp16 table. Each thread owns
// 4 consecutive samples (s % 4 == 0), so integer-phase quadrants are 0,1,2,3:
//   R[s+0]=( i, q)  R[s+1]=(-q, i)  R[s+2]=(-i,-q)  R[s+3]=( q,-i)
// Rotation is exact (sign/swap). Entry at a row end is never read by das.
// ---------------------------------------------------------------------------
__global__ __launch_bounds__(256)
void interleave_k(const float* __restrict__ id,
                  const float* __restrict__ qd) {
    int s = (blockIdx.x * blockDim.x + threadIdx.x) * 4;
    float4 a = *(const float4*)(id + s);
    float4 b = *(const float4*)(qd + s);
    int s4 = (s + 4 < NTOT) ? s + 4 : NTOT - 1;   // guarded lookahead sample
    float a4 = id[s4];
    float b4 = qd[s4];

    unsigned r0 = h2bits( a.x,  b.x);   // quadrant 0
    unsigned r1 = h2bits(-b.y,  a.y);   // quadrant 1
    unsigned r2 = h2bits(-a.z, -b.z);   // quadrant 2
    unsigned r3 = h2bits( b.w, -a.w);   // quadrant 3
    unsigned r4 = h2bits( a4,   b4);    // quadrant 0 (s+4)

    *(uint4*)(g_pair + s)     = make_uint4(r0, r1, r1, r2);  // entries s, s+1
    *(uint4*)(g_pair + s + 2) = make_uint4(r2, r3, r3, r4);  // entries s+2, s+3
}

// ---------------------------------------------------------------------------
// One element contribution (branchless): ONE LDG.64 fetches both pre-rotated
// endpoints; residual rotation rot((pi/2)*frac), frac in [0,1), direct MUFU
// sincos, no quadrant logic. NO bounds check: for keep=true lanes delay is
// provably in [93,1417] for this geometry, so the gather is always interior.
// ---------------------------------------------------------------------------
__device__ __forceinline__ void contrib(const float2* __restrict__ row,
                                        float delay, bool keep,
                                        float& ai, float& aq) {
    const int   i0   = __float2int_rd(delay);
    const float frac = delay - (float)i0;

    float2 raw = make_float2(0.0f, 0.0f);
    if (keep) raw = __ldg(row + i0);
    const float2 P0 = __half22float2(*reinterpret_cast<__half2*>(&raw.x));
    const float2 P1 = __half22float2(*reinterpret_cast<__half2*>(&raw.y));

    const float A = fmaf(frac, P1.y - P0.x, P0.x);   // (1-f)P0.x + f*P1.y
    const float B = fmaf(frac, -P1.x - P0.y, P0.y);  // (1-f)P0.y - f*P1.x

    const float targ = frac * HALF_PI_F;
    const float st = __sinf(targ);
    const float ct = __cosf(targ);

    ai += A * ct - B * st;
    aq += B * ct + A * st;
}

// ---------------------------------------------------------------------------
// Pass 2: main DAS. TWO threads per (pixel, angle): blockIdx.z = a*2 + half,
// each summing half the warp-uniform element range. Tile = 32(x) x 8(z)
// (R14 layout: warp = 32 consecutive x at ONE z -- single delay band per
// warp). txapo folded into zEff so the per-iter predicate is one compare.
// ---------------------------------------------------------------------------
__global__ __launch_bounds__(256)
void das_k(const float* __restrict__ grid,
           const float* __restrict__ angles,
           const float* __restrict__ ele,
           const float* __restrict__ tz) {
    __shared__ float sex[NELEM];
    int t = threadIdx.x;                     // tile = 32(x) x 8(z)
    if (t < NELEM) sex[t] = ele[t * 3];      // ele_pos[e,0]
    __syncthreads();

    const int a    = blockIdx.z >> 1;
    const int half = blockIdx.z & 1;
    const int ix = blockIdx.x * 32 + (t & 31);
    const int iz = blockIdx.y * 8  + (t >> 5);
    const int p  = iz * NX + ix;

    const float x = grid[3 * p + 0];
    const float z = grid[3 * p + 2];         // uniform within a warp

    const float ang = angles[a];
    const float sa = sinf(ang);
    const float ca = cosf(ang);
    const float ta = tanf(ang);

    const float txdel = (x * sa + z * ca + tz[a] * C_F) * FSoC;

    const float ex0 = sex[0];
    const float exN = sex[NELEM - 1];

    const float xproj = x - z * ta;
    const bool txapo = (xproj >= ex0 * 1.2f) && (xproj <= exN * 1.2f);
    const float zEff = txapo ? z : -1.0f;    // folds tx apod into the keep cmp

    float ai = 0.0f, aq = 0.0f;

    if (__any_sync(0xffffffffu, txapo)) {
        // warp-uniform element range from the warp's x window and z
        const float x_lo = __shfl_sync(0xffffffffu, x, 0);
        const float x_hi = __shfl_sync(0xffffffffu, x, 31);
        const float inv_pitch = 1.0f / (sex[1] - sex[0]);
        const float hz = 0.5f * z;
        int eLo = (int)floorf((x_lo - hz - ex0) * inv_pitch) - 1;
        int eHi = (int)ceilf ((x_hi + hz - ex0) * inv_pitch) + 1;
        eLo = eLo < 0 ? 0 : eLo;
        eHi = eHi > NELEM - 1 ? NELEM - 1 : eHi;

        // split the range across the two halves (warp-uniform)
        const int mid = (eLo + eHi + 1) >> 1;
        const int e0 = half ? mid : eLo;
        const int e1 = half ? eHi : (mid - 1);

        const float zz = z * z;
        const float2* __restrict__ row =
            g_pair + ((size_t)a * NELEM + e0) * NSAMP;

        #pragma unroll 8
        for (int e = e0; e <= e1; e++) {
            const float vx  = x - sex[e];           // exact, matches reference
            const bool keep = zEff > 2.0f * fabsf(vx);
            const float r2  = fmaf(vx, vx, zz);
            const float delay = fmaf(r2 * rsqrtf(r2), FSoC, txdel);
            contrib(row, delay, keep, ai, aq);
            row += NSAMP;
        }
    }

    g_acc[blockIdx.z * 2 + 0][p] = ai;
    g_acc[blockIdx.z * 2 + 1][p] = aq;
}

// ---------------------------------------------------------------------------
// Pass 3: sum the 8 (angle,half) partials + deferred pixel-constant rotation
// phi(z) = -4*pi*FDEMOD*z/C (accurate sincosf, large argument).
// ---------------------------------------------------------------------------
__global__ void reduce_k(const float* __restrict__ grid,
                         float* __restrict__ out) {
    int p = blockIdx.x * blockDim.x + threadIdx.x;
    if (p >= NPIX) return;
    float ai = 0.0f, aq = 0.0f;
    #pragma unroll
    for (int s = 0; s < NANG * 2; s++) {
        ai += g_acc[s * 2 + 0][p];
        aq += g_acc[s * 2 + 1][p];
    }
    const float z = grid[3 * p + 2];
    const float phi = (-4.0f * PI_F * FDEMOD_F / C_F) * z;
    float sb, cb;
    sincosf(phi, &sb, &cb);
    out[p]        = ai * cb - aq * sb;   // idas
    out[NPIX + p] = aq * cb + ai * sb;   // qdas
}

extern "C" void kernel_launch(void* const* d_in, const int* in_sizes, int n_in,
                              void* d_out, int out_size) {
    const float* idata  = (const float*)d_in[0];
    const float* qdata  = (const float*)d_in[1];
    const float* grid   = (const float*)d_in[2];
    const float* angles = (const float*)d_in[3];
    const float* ele    = (const float*)d_in[4];
    const float* tz     = (const float*)d_in[5];

    interleave_k<<<NTOT / (256 * 4), 256>>>(idata, qdata);

    dim3 g(NX / 32, NZ / 8, NANG * 2);             // 6 x 24 x 8 = 1152 blocks
    das_k<<<g, 256>>>(grid, angles, ele, tz);

    reduce_k<<<(NPIX + 255) / 256, 256>>>(grid, (float*)d_out);
}

// round 17
// speedup vs baseline: 1.0683x; 1.0683x over previous
#include <cuda_runtime.h>
#include <cuda_fp16.h>

#define NANG  4
#define NELEM 128
#define NZ    192
#define NX    192
#define NPIX  (NZ * NX)
#define NSAMP 2048
#define NTOT  (NANG * NELEM * NSAMP)

#define PI_F      3.14159265359f
#define HALF_PI_F 1.57079632679f
#define FS_F      20832000.0f
#define C_F       1540.0f
#define FDEMOD_F  5208000.0f
#define FSoC      (FS_F / C_F)

// Scratch (static device globals -- no allocation)
// g_iq[s] = R[s] = rot((pi/2)*s) . (i[s], q[s]) as one half2 (4 B/sample).
// NOT pair-duplicated: the two lerp endpoints come from two LDG.32 that hit
// the same L2 sectors (dedup'd), halving L2 sector traffic vs the 8B pairs.
__device__ __half2 g_iq[NTOT];                  // 4 MB
__device__ float   g_acc[NANG * 4][NPIX];       // per-(angle,half) partials

// ---------------------------------------------------------------------------
// Pass 1: build the PRE-ROTATED fp16 table. Each thread owns 4 consecutive
// samples (s % 4 == 0), so integer-phase quadrants are exactly 0,1,2,3:
//   R[s+0]=( i, q)  R[s+1]=(-q, i)  R[s+2]=(-i,-q)  R[s+3]=( q,-i)
// Rotation is exact (sign/swap).
// ---------------------------------------------------------------------------
__global__ __launch_bounds__(256)
void interleave_k(const float* __restrict__ id,
                  const float* __restrict__ qd) {
    int s = (blockIdx.x * blockDim.x + threadIdx.x) * 4;
    float4 a = *(const float4*)(id + s);
    float4 b = *(const float4*)(qd + s);

    __half2 r0 = __floats2half2_rn( a.x,  b.x);   // quadrant 0
    __half2 r1 = __floats2half2_rn(-b.y,  a.y);   // quadrant 1
    __half2 r2 = __floats2half2_rn(-a.z, -b.z);   // quadrant 2
    __half2 r3 = __floats2half2_rn( b.w, -a.w);   // quadrant 3

    uint4 packed = make_uint4(*reinterpret_cast<unsigned*>(&r0),
                              *reinterpret_cast<unsigned*>(&r1),
                              *reinterpret_cast<unsigned*>(&r2),
                              *reinterpret_cast<unsigned*>(&r3));
    *(uint4*)(g_iq + s) = packed;
}

// ---------------------------------------------------------------------------
// One element contribution (branchless): two LDG.32 fetch the pre-rotated
// endpoints R[i0], R[i0+1]; residual rotation rot((pi/2)*frac), frac in
// [0,1), direct MUFU sincos, no quadrant logic. NO bounds check: for
// keep=true lanes delay is provably in [93,1417] for this geometry.
//   contribution = rot(pi/2*f) . [ (1-f)P0 + f*(P1.y, -P1.x) ]
// ---------------------------------------------------------------------------
__device__ __forceinline__ void contrib(const __half2* __restrict__ row,
                                        float delay, bool keep,
                                        float& ai, float& aq) {
    const int   i0   = __float2int_rd(delay);
    const float frac = delay - (float)i0;

    __half2 h0 = __floats2half2_rn(0.0f, 0.0f);
    __half2 h1 = h0;
    if (keep) {
        h0 = __ldg(row + i0);
        h1 = __ldg(row + i0 + 1);
    }
    const float2 P0 = __half22float2(h0);
    const float2 P1 = __half22float2(h1);

    const float A = fmaf(frac, P1.y - P0.x, P0.x);   // (1-f)P0.x + f*P1.y
    const float B = fmaf(frac, -P1.x - P0.y, P0.y);  // (1-f)P0.y - f*P1.x

    const float targ = frac * HALF_PI_F;
    const float st = __sinf(targ);
    const float ct = __cosf(targ);

    ai += A * ct - B * st;
    aq += B * ct + A * st;
}

// ---------------------------------------------------------------------------
// Pass 2: main DAS. TWO threads per (pixel, angle): blockIdx.z = a*2 + half,
// each summing half the warp-uniform element range. Tile = 32(x) x 8(z)
// (warp = 32 consecutive x at ONE z -- single delay band per warp). txapo
// folded into zEff so the per-iter predicate is one compare.
// ---------------------------------------------------------------------------
__global__ __launch_bounds__(256)
void das_k(const float* __restrict__ grid,
           const float* __restrict__ angles,
           const float* __restrict__ ele,
           const float* __restrict__ tz) {
    __shared__ float sex[NELEM];
    int t = threadIdx.x;                     // tile = 32(x) x 8(z)
    if (t < NELEM) sex[t] = ele[t * 3];      // ele_pos[e,0]
    __syncthreads();

    const int a    = blockIdx.z >> 1;
    const int half = blockIdx.z & 1;
    const int ix = blockIdx.x * 32 + (t & 31);
    const int iz = blockIdx.y * 8  + (t >> 5);
    const int p  = iz * NX + ix;

    const float x = grid[3 * p + 0];
    const float z = grid[3 * p + 2];         // uniform within a warp

    const float ang = angles[a];
    const float sa = sinf(ang);
    const float ca = cosf(ang);
    const float ta = tanf(ang);

    const float txdel = (x * sa + z * ca + tz[a] * C_F) * FSoC;

    const float ex0 = sex[0];
    const float exN = sex[NELEM - 1];

    const float xproj = x - z * ta;
    const bool txapo = (xproj >= ex0 * 1.2f) && (xproj <= exN * 1.2f);
    const float zEff = txapo ? z : -1.0f;    // folds tx apod into the keep cmp

    float ai = 0.0f, aq = 0.0f;

    if (__any_sync(0xffffffffu, txapo)) {
        // warp-uniform element range from the warp's x window and z
        const float x_lo = __shfl_sync(0xffffffffu, x, 0);
        const float x_hi = __shfl_sync(0xffffffffu, x, 31);
        const float inv_pitch = 1.0f / (sex[1] - sex[0]);
        const float hz = 0.5f * z;
        int eLo = (int)floorf((x_lo - hz - ex0) * inv_pitch) - 1;
        int eHi = (int)ceilf ((x_hi + hz - ex0) * inv_pitch) + 1;
        eLo = eLo < 0 ? 0 : eLo;
        eHi = eHi > NELEM - 1 ? NELEM - 1 : eHi;

        // split the range across the two halves (warp-uniform)
        const int mid = (eLo + eHi + 1) >> 1;
        const int e0 = half ? mid : eLo;
        const int e1 = half ? eHi : (mid - 1);

        const float zz = z * z;
        const __half2* __restrict__ row =
            g_iq + ((size_t)a * NELEM + e0) * NSAMP;

        #pragma unroll 8
        for (int e = e0; e <= e1; e++) {
            const float vx  = x - sex[e];           // exact, matches reference
            const bool keep = zEff > 2.0f * fabsf(vx);
            const float r2  = fmaf(vx, vx, zz);
            const float delay = fmaf(r2 * rsqrtf(r2), FSoC, txdel);
            contrib(row, delay, keep, ai, aq);
            row += NSAMP;
        }
    }

    g_acc[blockIdx.z * 2 + 0][p] = ai;
    g_acc[blockIdx.z * 2 + 1][p] = aq;
}

// ---------------------------------------------------------------------------
// Pass 3: sum the 8 (angle,half) partials + deferred pixel-constant rotation
// phi(z) = -4*pi*FDEMOD*z/C (accurate sincosf, large argument).
// ---------------------------------------------------------------------------
__global__ void reduce_k(const float* __restrict__ grid,
                         float* __restrict__ out) {
    int p = blockIdx.x * blockDim.x + threadIdx.x;
    if (p >= NPIX) return;
    float ai = 0.0f, aq = 0.0f;
    #pragma unroll
    for (int s = 0; s < NANG * 2; s++) {
        ai += g_acc[s * 2 + 0][p];
        aq += g_acc[s * 2 + 1][p];
    }
    const float z = grid[3 * p + 2];
    const float phi = (-4.0f * PI_F * FDEMOD_F / C_F) * z;
    float sb, cb;
    sincosf(phi, &sb, &cb);
    out[p]        = ai * cb - aq * sb;   // idas
    out[NPIX + p] = aq * cb + ai * sb;   // qdas
}

extern "C" void kernel_launch(void* const* d_in, const int* in_sizes, int n_in,
                              void* d_out, int out_size) {
    const float* idata  = (const float*)d_in[0];
    const float* qdata  = (const float*)d_in[1];
    const float* grid   = (const float*)d_in[2];
    const float* angles = (const float*)d_in[3];
    const float* ele    = (const float*)d_in[4];
    const float* tz     = (const float*)d_in[5];

    interleave_k<<<NTOT / (256 * 4), 256>>>(idata, qdata);

    dim3 g(NX / 32, NZ / 8, NANG * 2);             // 6 x 24 x 8 = 1152 blocks
    das_k<<<g, 256>>>(grid, angles, ele, tz);

    reduce_k<<<(NPIX + 255) / 256, 256>>>(grid, (float*)d_out);
}